// round 13
// baseline (speedup 1.0000x reference)
#include <cuda_runtime.h>
#include <cuda_fp16.h>
#include <stdint.h>
#include <math.h>

// Problem constants
static constexpr int BB   = 2;
static constexpr int SS   = 2048;
static constexpr int HH   = 1024;
static constexpr int NH   = 16;
static constexpr int HD   = 64;
static constexpr int MTOT = BB * SS;  // 4096 rows

// Scratch (static device globals)
__device__ __align__(16) __half g_xh [(size_t)MTOT * HH];   // x in fp16
__device__ __align__(16) __half g_Wqh[(size_t)HH * HH];
__device__ __align__(16) __half g_Wkh[(size_t)HH * HH];
__device__ __align__(16) __half g_Wvh[(size_t)HH * HH];
__device__ __align__(16) __half g_Woh[(size_t)HH * HH];
__device__ __align__(16) __half g_Q[(size_t)BB * NH * SS * HD];  // pre-scaled 0.125
__device__ __align__(16) __half g_K[(size_t)BB * NH * SS * HD];
__device__ __align__(16) __half g_V[(size_t)BB * NH * SS * HD];
__device__ __align__(16) __half g_ctx[(size_t)MTOT * HH];        // fp16 ctx
__device__ float  g_y[(size_t)MTOT * HH];

// ---------------------------------------------------------------------------
// helpers
// ---------------------------------------------------------------------------
__device__ __forceinline__ uint32_t pack2h(float lo, float hi) {
    uint32_t r;
    asm("cvt.rn.f16x2.f32 %0, %1, %2;" : "=r"(r) : "f"(hi), "f"(lo));
    return r;
}
__device__ __forceinline__ void mma16(float c[4], const uint32_t a[4], const uint32_t b[2]) {
    asm volatile(
        "mma.sync.aligned.m16n8k16.row.col.f32.f16.f16.f32 "
        "{%0,%1,%2,%3}, {%4,%5,%6,%7}, {%8,%9}, {%0,%1,%2,%3};"
        : "+f"(c[0]), "+f"(c[1]), "+f"(c[2]), "+f"(c[3])
        : "r"(a[0]), "r"(a[1]), "r"(a[2]), "r"(a[3]), "r"(b[0]), "r"(b[1]));
}
__device__ __forceinline__ void ldsm4(uint32_t r[4], const __half* p) {
    uint32_t a = (uint32_t)__cvta_generic_to_shared(p);
    asm volatile("ldmatrix.sync.aligned.m8n8.x4.shared.b16 {%0,%1,%2,%3}, [%4];"
        : "=r"(r[0]), "=r"(r[1]), "=r"(r[2]), "=r"(r[3]) : "r"(a));
}
__device__ __forceinline__ void ldsm4t(uint32_t r[4], const __half* p) {
    uint32_t a = (uint32_t)__cvta_generic_to_shared(p);
    asm volatile("ldmatrix.sync.aligned.m8n8.x4.trans.shared.b16 {%0,%1,%2,%3}, [%4];"
        : "=r"(r[0]), "=r"(r[1]), "=r"(r[2]), "=r"(r[3]) : "r"(a));
}
__device__ __forceinline__ void cp16(__half* dst, const __half* src) {
    uint32_t d = (uint32_t)__cvta_generic_to_shared(dst);
    asm volatile("cp.async.cg.shared.global [%0], [%1], 16;" :: "r"(d), "l"(src));
}
__device__ __forceinline__ void cp_commit() {
    asm volatile("cp.async.commit_group;");
}
template <int N> __device__ __forceinline__ void cp_wait() {
    asm volatile("cp.async.wait_group %0;" :: "n"(N));
}

// ---------------------------------------------------------------------------
// fp32 -> fp16 pre-conversion of x and weights (one pass).
// grid: (4096, 1, 5); z selects tensor.
// ---------------------------------------------------------------------------
__global__ __launch_bounds__(256) void cvt_kernel(
    const float* __restrict__ x,
    const float* __restrict__ wq, const float* __restrict__ wk,
    const float* __restrict__ wv, const float* __restrict__ wo)
{
    const int z = blockIdx.z;
    const float* src;
    __half* dst;
    int n4;
    if      (z == 0) { src = x;  dst = g_xh;  n4 = MTOT * HH / 4; }
    else if (z == 1) { src = wq; dst = g_Wqh; n4 = HH * HH / 4; }
    else if (z == 2) { src = wk; dst = g_Wkh; n4 = HH * HH / 4; }
    else if (z == 3) { src = wv; dst = g_Wvh; n4 = HH * HH / 4; }
    else             { src = wo; dst = g_Woh; n4 = HH * HH / 4; }
    const int idx = blockIdx.x * 256 + threadIdx.x;
    if (idx < n4) {
        float4 v = ((const float4*)src)[idx];
        uint2 o;
        o.x = pack2h(v.x, v.y);
        o.y = pack2h(v.z, v.w);
        ((uint2*)dst)[idx] = o;
    }
}

// ---------------------------------------------------------------------------
// 128x128x1024 fp16 mma mainloop, cp.async double-buffered, LDSM frags.
// 256 threads, 8 warps (2m x 4n), warp tile 64x32, mma m16n8k16, BK=32.
// A, B are fp16 in gmem (A row-major [M][HH], B row-major [HH][N]).
// ---------------------------------------------------------------------------
static constexpr int AS_ST = 40;
static constexpr int BS_ST = 136;
static constexpr int ABUF  = 128 * AS_ST;   // 5120 halfs
static constexpr int BBUF  = 32 * BS_ST;    // 4352 halfs

__device__ __forceinline__ void gemm128_mainloop_h(
    const __half* __restrict__ A, const __half* __restrict__ B,
    __half* As, __half* Bs, float acc[4][4][4])
{
    const int tid  = threadIdx.x;
    const int m0   = blockIdx.y * 128;
    const int n0   = blockIdx.x * 128;
    const int warp = tid >> 5;
    const int lane = tid & 31;
    const int warp_m = (warp >> 2) * 64;
    const int warp_n = (warp & 3) * 32;

    const int la = lane & 15, lb = lane >> 4;
    const __half* aF = As + (warp_m + la) * AS_ST + lb * 8;
    const __half* bF = Bs + la * BS_ST + warp_n + lb * 8;

#pragma unroll
    for (int mt = 0; mt < 4; mt++)
#pragma unroll
        for (int nt = 0; nt < 4; nt++)
#pragma unroll
            for (int r = 0; r < 4; r++) acc[mt][nt][r] = 0.0f;

    auto stage = [&](int k0, int buf) {
        __half* Ad = As + buf * ABUF;
        __half* Bd = Bs + buf * BBUF;
#pragma unroll
        for (int i = 0; i < 2; i++) {
            int u = tid + i * 256;             // 0..511
            int ar = u >> 2, ac = u & 3;       // A: 128 rows x 4 chunks
            cp16(Ad + ar * AS_ST + ac * 8,
                 A + (size_t)(m0 + ar) * HH + k0 + ac * 8);
            int br = u >> 4, bc = u & 15;      // B: 32 rows x 16 chunks
            cp16(Bd + br * BS_ST + bc * 8,
                 B + (size_t)(k0 + br) * HH + n0 + bc * 8);
        }
    };

    stage(0, 0);  cp_commit();
    stage(32, 1); cp_commit();

    int cur = 0;
    for (int k0 = 0; k0 < HH; k0 += 32) {
        cp_wait<1>();
        __syncthreads();

        const __half* aFc = aF + cur * ABUF;
        const __half* bFc = bF + cur * BBUF;
#pragma unroll
        for (int ks = 0; ks < 2; ks++) {
            uint32_t Af[4][4];
#pragma unroll
            for (int mt = 0; mt < 4; mt++)
                ldsm4(Af[mt], aFc + mt * 16 * AS_ST + ks * 16);
            uint32_t Bf[4][4];
#pragma unroll
            for (int ntp = 0; ntp < 2; ntp++)
                ldsm4t(Bf[2 * ntp], bFc + ks * 16 * BS_ST + ntp * 16);
#pragma unroll
            for (int mt = 0; mt < 4; mt++) {
                mma16(acc[mt][0], Af[mt], &Bf[0][0]);
                mma16(acc[mt][1], Af[mt], &Bf[0][2]);
                mma16(acc[mt][2], Af[mt], &Bf[2][0]);
                mma16(acc[mt][3], Af[mt], &Bf[2][2]);
            }
        }
        __syncthreads();

        if (k0 + 64 < HH) stage(k0 + 64, cur);
        cp_commit();
        cur ^= 1;
    }
}

// ---------------------------------------------------------------------------
// QKV GEMM: out = x @ W + b (Q scaled by 0.125), fp16 out, head-major scatter.
// ---------------------------------------------------------------------------
__global__ __launch_bounds__(256, 2) void qkv_gemm_kernel(
    const float* __restrict__ bq, const float* __restrict__ bk,
    const float* __restrict__ bv)
{
    const int mat = blockIdx.z;
    const __half* W   = (mat == 0) ? g_Wqh : (mat == 1 ? g_Wkh : g_Wvh);
    const float* bias = (mat == 0) ? bq : (mat == 1 ? bk : bv);
    __half* out       = (mat == 0) ? g_Q : (mat == 1 ? g_K : g_V);
    const float osc   = (mat == 0) ? 0.125f : 1.0f;

    __shared__ __align__(16) __half As[2 * ABUF];
    __shared__ __align__(16) __half Bs[2 * BBUF];

    float acc[4][4][4];
    gemm128_mainloop_h(g_xh, W, As, Bs, acc);

    const int tid  = threadIdx.x;
    const int warp = tid >> 5;
    const int lane = tid & 31;
    const int gid  = lane >> 2;
    const int t4   = lane & 3;
    const int warp_m = (warp >> 2) * 64;
    const int warp_n = (warp & 3) * 32;
    const int m0 = blockIdx.y * 128;
    const int n0 = blockIdx.x * 128;

#pragma unroll
    for (int mt = 0; mt < 4; mt++) {
        const int mrow = m0 + warp_m + mt * 16 + gid;
#pragma unroll
        for (int nt = 0; nt < 4; nt++) {
            const int n = n0 + warp_n + nt * 8 + t4 * 2;
            const int h = n >> 6;
            const int d = n & 63;
            const float bx = bias[n], by = bias[n + 1];
            {
                int b = mrow >> 11, s = mrow & 2047;
                __half* o = out + (((size_t)(b * NH + h) * SS) + s) * HD + d;
                *(uint32_t*)o = pack2h((acc[mt][nt][0] + bx) * osc,
                                       (acc[mt][nt][1] + by) * osc);
            }
            {
                int m2 = mrow + 8;
                int b = m2 >> 11, s = m2 & 2047;
                __half* o = out + (((size_t)(b * NH + h) * SS) + s) * HD + d;
                *(uint32_t*)o = pack2h((acc[mt][nt][2] + bx) * osc,
                                       (acc[mt][nt][3] + by) * osc);
            }
        }
    }
}

// ---------------------------------------------------------------------------
// Flash attention, fp16 m16n8k16, cp.async double-buffered K/V, LDSM frags.
// 256 threads (8 warps) -> 128 q rows. smem 36.9 KB -> 2 CTAs/SM.
// ---------------------------------------------------------------------------
static constexpr int FK_ST = 72;              // halfs per row
static constexpr int KVBUF = 64 * FK_ST;      // 4608 halfs

__global__ __launch_bounds__(256, 2) void flash_tc_kernel()
{
    __shared__ __align__(16) __half sm[4 * KVBUF];   // 36.9 KB

    const int bh  = blockIdx.y;     // b*NH + h
    const int b   = bh >> 4;
    const int h   = bh & 15;
    const int q0  = blockIdx.x * 128;
    const int tid = threadIdx.x;
    const int warp = tid >> 5;
    const int lane = tid & 31;
    const int gid  = lane >> 2;
    const int t4   = lane & 3;
    const int la   = lane & 15;
    const int lb   = lane >> 4;
    const unsigned F = 0xFFFFFFFFu;

    // ---- Stage Q, extract frags ----
    {
        const uint2* Qg = (const uint2*)(g_Q + ((size_t)bh * SS + q0) * HD);
#pragma unroll
        for (int i = 0; i < 8; i++) {
            int idx = tid + i * 256;
            int row = idx >> 4, c4 = idx & 15;
            *(uint2*)&sm[row * FK_ST + c4 * 4] = Qg[idx];
        }
    }
    __syncthreads();

    uint32_t Qa[4][4];
    {
        const __half* qF = sm + (warp * 16 + la) * FK_ST + lb * 8;
#pragma unroll
        for (int ks = 0; ks < 4; ks++)
            ldsm4(Qa[ks], qF + ks * 16);
    }
    __syncthreads();

    float Oc[8][4];
#pragma unroll
    for (int dt = 0; dt < 8; dt++)
#pragma unroll
        for (int r = 0; r < 4; r++) Oc[dt][r] = 0.0f;
    float m0r = -1e30f, m1r = -1e30f;
    float l0r = 0.0f,   l1r = 0.0f;

    const __half* Kgb = g_K + (size_t)bh * SS * HD;
    const __half* Vgb = g_V + (size_t)bh * SS * HD;

    const int krow_l = (lane & 7) + lb * 8;
    const int kcol_l = ((lane >> 3) & 1) * 8;

    auto issue = [&](int kt, int buf) {
        __half* Kd = sm + buf * 2 * KVBUF;
        __half* Vd = Kd + KVBUF;
        const __half* Kg = Kgb + (size_t)kt * 64 * HD;
        const __half* Vg = Vgb + (size_t)kt * 64 * HD;
#pragma unroll
        for (int i = 0; i < 2; i++) {
            int u = tid + i * 256;
            int row = u >> 3, c8 = u & 7;
            cp16(Kd + row * FK_ST + c8 * 8, Kg + row * 64 + c8 * 8);
            cp16(Vd + row * FK_ST + c8 * 8, Vg + row * 64 + c8 * 8);
        }
        cp_commit();
    };

    issue(0, 0);

    for (int kt = 0; kt < SS / 64; kt++) {
        const bool more = (kt + 1 < SS / 64);
        if (more) issue(kt + 1, (kt + 1) & 1);
        if (more) cp_wait<1>(); else cp_wait<0>();
        __syncthreads();

        const __half* Ks = sm + (kt & 1) * 2 * KVBUF;
        const __half* Vs = Ks + KVBUF;

        // ---- S = Q K^T ----
        float S[8][4];
#pragma unroll
        for (int nt = 0; nt < 8; nt++)
            S[nt][0] = S[nt][1] = S[nt][2] = S[nt][3] = 0.0f;
#pragma unroll
        for (int ks = 0; ks < 4; ks++) {
#pragma unroll
            for (int ntp = 0; ntp < 4; ntp++) {
                uint32_t bb[4];
                ldsm4(bb, Ks + (ntp * 16 + krow_l) * FK_ST + ks * 16 + kcol_l);
                mma16(S[2 * ntp],     Qa[ks], bb);
                mma16(S[2 * ntp + 1], Qa[ks], bb + 2);
            }
        }

        // ---- clip + online softmax ----
        float tmax0 = -1e30f, tmax1 = -1e30f;
#pragma unroll
        for (int nt = 0; nt < 8; nt++) {
#pragma unroll
            for (int r = 0; r < 4; r++)
                S[nt][r] = fminf(fmaxf(S[nt][r], -10000.0f), 10000.0f);
            tmax0 = fmaxf(tmax0, fmaxf(S[nt][0], S[nt][1]));
            tmax1 = fmaxf(tmax1, fmaxf(S[nt][2], S[nt][3]));
        }
        tmax0 = fmaxf(tmax0, __shfl_xor_sync(F, tmax0, 1));
        tmax0 = fmaxf(tmax0, __shfl_xor_sync(F, tmax0, 2));
        tmax1 = fmaxf(tmax1, __shfl_xor_sync(F, tmax1, 1));
        tmax1 = fmaxf(tmax1, __shfl_xor_sync(F, tmax1, 2));

        float nm0 = fmaxf(m0r, tmax0);
        float nm1 = fmaxf(m1r, tmax1);
        float al0 = __expf(m0r - nm0);
        float al1 = __expf(m1r - nm1);
        m0r = nm0; m1r = nm1;

        float sum0 = 0.0f, sum1 = 0.0f;
#pragma unroll
        for (int nt = 0; nt < 8; nt++) {
            S[nt][0] = __expf(S[nt][0] - nm0);
            S[nt][1] = __expf(S[nt][1] - nm0);
            S[nt][2] = __expf(S[nt][2] - nm1);
            S[nt][3] = __expf(S[nt][3] - nm1);
            sum0 += S[nt][0] + S[nt][1];
            sum1 += S[nt][2] + S[nt][3];
        }
        sum0 += __shfl_xor_sync(F, sum0, 1);
        sum0 += __shfl_xor_sync(F, sum0, 2);
        sum1 += __shfl_xor_sync(F, sum1, 1);
        sum1 += __shfl_xor_sync(F, sum1, 2);
        l0r = l0r * al0 + sum0;
        l1r = l1r * al1 + sum1;

#pragma unroll
        for (int dt = 0; dt < 8; dt++) {
            Oc[dt][0] *= al0; Oc[dt][1] *= al0;
            Oc[dt][2] *= al1; Oc[dt][3] *= al1;
        }

        // ---- ctx += P V ----
#pragma unroll
        for (int ks = 0; ks < 4; ks++) {
            uint32_t Pa[4];
            Pa[0] = pack2h(S[2 * ks][0],     S[2 * ks][1]);
            Pa[1] = pack2h(S[2 * ks][2],     S[2 * ks][3]);
            Pa[2] = pack2h(S[2 * ks + 1][0], S[2 * ks + 1][1]);
            Pa[3] = pack2h(S[2 * ks + 1][2], S[2 * ks + 1][3]);
            const __half* vrow = Vs + (ks * 16 + la) * FK_ST + lb * 8;
#pragma unroll
            for (int dtp = 0; dtp < 4; dtp++) {
                uint32_t bb[4];
                ldsm4t(bb, vrow + dtp * 16);
                mma16(Oc[2 * dtp],     Pa, bb);
                mma16(Oc[2 * dtp + 1], Pa, bb + 2);
            }
        }
        __syncthreads();
    }

    // ---- epilogue: normalize, write fp16 ctx ----
    const float inv0 = 1.0f / l0r;
    const float inv1 = 1.0f / l1r;
    const int srow = q0 + warp * 16 + gid;
    __half* out0 = g_ctx + ((size_t)(b * SS + srow)) * HH + h * HD;
    __half* out1 = out0 + (size_t)8 * HH;
#pragma unroll
    for (int dt = 0; dt < 8; dt++) {
        int c = dt * 8 + t4 * 2;
        *(uint32_t*)(out0 + c) = pack2h(Oc[dt][0] * inv0, Oc[dt][1] * inv0);
        *(uint32_t*)(out1 + c) = pack2h(Oc[dt][2] * inv1, Oc[dt][3] * inv1);
    }
}

// ---------------------------------------------------------------------------
// O projection: y = ctx @ Wo + bo + x   (ctx fp16, Wo fp16, residual fp32)
// ---------------------------------------------------------------------------
__global__ __launch_bounds__(256, 2) void oproj_gemm_kernel(
    const float* __restrict__ x, const float* __restrict__ bo)
{
    __shared__ __align__(16) __half As[2 * ABUF];
    __shared__ __align__(16) __half Bs[2 * BBUF];

    float acc[4][4][4];
    gemm128_mainloop_h(g_ctx, g_Woh, As, Bs, acc);

    const int tid  = threadIdx.x;
    const int warp = tid >> 5;
    const int lane = tid & 31;
    const int gid  = lane >> 2;
    const int t4   = lane & 3;
    const int warp_m = (warp >> 2) * 64;
    const int warp_n = (warp & 3) * 32;
    const int m0 = blockIdx.y * 128;
    const int n0 = blockIdx.x * 128;

#pragma unroll
    for (int mt = 0; mt < 4; mt++) {
        const int mrow = m0 + warp_m + mt * 16 + gid;
#pragma unroll
        for (int nt = 0; nt < 4; nt++) {
            const int n = n0 + warp_n + nt * 8 + t4 * 2;
            const float bx = bo[n], by = bo[n + 1];
            {
                const float* xr = x + (size_t)mrow * HH + n;
                float* yo = g_y + (size_t)mrow * HH + n;
                *(float2*)yo = make_float2(acc[mt][nt][0] + bx + xr[0],
                                           acc[mt][nt][1] + by + xr[1]);
            }
            {
                const float* xr = x + (size_t)(mrow + 8) * HH + n;
                float* yo = g_y + (size_t)(mrow + 8) * HH + n;
                *(float2*)yo = make_float2(acc[mt][nt][2] + bx + xr[0],
                                           acc[mt][nt][3] + by + xr[1]);
            }
        }
    }
}

// ---------------------------------------------------------------------------
// LayerNorm over last dim (1024): shuffle reduce, one sync.
// ---------------------------------------------------------------------------
__global__ __launch_bounds__(256) void ln_kernel(
    const float* __restrict__ gamma, const float* __restrict__ beta,
    float* __restrict__ out)
{
    __shared__ float red[16];
    const int row = blockIdx.x;
    const int tid = threadIdx.x;
    const int warp = tid >> 5;
    const int lane = tid & 31;
    const unsigned F = 0xFFFFFFFFu;

    const float4* yp = (const float4*)(g_y + (size_t)row * HH);
    float4 v = yp[tid];

    float s  = v.x + v.y + v.z + v.w;
    float sq = v.x * v.x + v.y * v.y + v.z * v.z + v.w * v.w;
#pragma unroll
    for (int off = 16; off > 0; off >>= 1) {
        s  += __shfl_xor_sync(F, s,  off);
        sq += __shfl_xor_sync(F, sq, off);
    }
    if (lane == 0) { red[warp] = s; red[8 + warp] = sq; }
    __syncthreads();

    float ts = 0.0f, tsq = 0.0f;
#pragma unroll
    for (int w = 0; w < 8; w++) { ts += red[w]; tsq += red[8 + w]; }
    const float mu  = ts * (1.0f / HH);
    const float var = tsq * (1.0f / HH) - mu * mu;
    const float inv = rsqrtf(var + 1e-5f);

    const float4 g  = ((const float4*)gamma)[tid];
    const float4 be = ((const float4*)beta)[tid];
    float4 o;
    o.x = (v.x - mu) * inv * g.x + be.x;
    o.y = (v.y - mu) * inv * g.y + be.y;
    o.z = (v.z - mu) * inv * g.z + be.z;
    o.w = (v.w - mu) * inv * g.w + be.w;
    ((float4*)out)[(size_t)row * (HH / 4) + tid] = o;
}

// ---------------------------------------------------------------------------
extern "C" void kernel_launch(void* const* d_in, const int* in_sizes, int n_in,
                              void* d_out, int out_size)
{
    (void)in_sizes; (void)n_in; (void)out_size;
    const float* x  = (const float*)d_in[0];
    const float* Wq = (const float*)d_in[1];
    const float* bq = (const float*)d_in[2];
    const float* Wk = (const float*)d_in[3];
    const float* bk = (const float*)d_in[4];
    const float* Wv = (const float*)d_in[5];
    const float* bv = (const float*)d_in[6];
    const float* Wo = (const float*)d_in[7];
    const float* bo = (const float*)d_in[8];
    const float* ga = (const float*)d_in[9];
    const float* be = (const float*)d_in[10];
    float* out = (float*)d_out;

    dim3 gc(4096, 1, 5);
    cvt_kernel<<<gc, 256>>>(x, Wq, Wk, Wv, Wo);

    dim3 gq(HH / 128, MTOT / 128, 3);
    qkv_gemm_kernel<<<gq, 256>>>(bq, bk, bv);

    dim3 gf(SS / 128, BB * NH);
    flash_tc_kernel<<<gf, 256>>>();

    dim3 go(HH / 128, MTOT / 128);
    oproj_gemm_kernel<<<go, 256>>>(x, bo);

    ln_kernel<<<MTOT, 256>>>(ga, be, out);
}

// round 14
// speedup vs baseline: 1.3783x; 1.3783x over previous
#include <cuda_runtime.h>
#include <cuda_fp16.h>
#include <stdint.h>
#include <math.h>

// Problem constants
static constexpr int BB   = 2;
static constexpr int SS   = 2048;
static constexpr int HH   = 1024;
static constexpr int NH   = 16;
static constexpr int HD   = 64;
static constexpr int MTOT = BB * SS;  // 4096 rows

// Scratch (static device globals)
__device__ __align__(16) __half g_xh [(size_t)MTOT * HH];   // x in fp16
__device__ __align__(16) __half g_Wqh[(size_t)HH * HH];
__device__ __align__(16) __half g_Wkh[(size_t)HH * HH];
__device__ __align__(16) __half g_Wvh[(size_t)HH * HH];
__device__ __align__(16) __half g_Woh[(size_t)HH * HH];
__device__ __align__(16) __half g_Q[(size_t)BB * NH * SS * HD];  // pre-scaled 0.125
__device__ __align__(16) __half g_K[(size_t)BB * NH * SS * HD];
__device__ __align__(16) __half g_V[(size_t)BB * NH * SS * HD];
__device__ __align__(16) __half g_ctx[(size_t)MTOT * HH];        // fp16 ctx
__device__ float  g_y[(size_t)MTOT * HH];

// ---------------------------------------------------------------------------
// helpers
// ---------------------------------------------------------------------------
__device__ __forceinline__ uint32_t pack2h(float lo, float hi) {
    uint32_t r;
    asm("cvt.rn.f16x2.f32 %0, %1, %2;" : "=r"(r) : "f"(hi), "f"(lo));
    return r;
}
__device__ __forceinline__ void mma16(float c[4], const uint32_t a[4], const uint32_t b[2]) {
    asm volatile(
        "mma.sync.aligned.m16n8k16.row.col.f32.f16.f16.f32 "
        "{%0,%1,%2,%3}, {%4,%5,%6,%7}, {%8,%9}, {%0,%1,%2,%3};"
        : "+f"(c[0]), "+f"(c[1]), "+f"(c[2]), "+f"(c[3])
        : "r"(a[0]), "r"(a[1]), "r"(a[2]), "r"(a[3]), "r"(b[0]), "r"(b[1]));
}
__device__ __forceinline__ void ldsm4(uint32_t r[4], const __half* p) {
    uint32_t a = (uint32_t)__cvta_generic_to_shared(p);
    asm volatile("ldmatrix.sync.aligned.m8n8.x4.shared.b16 {%0,%1,%2,%3}, [%4];"
        : "=r"(r[0]), "=r"(r[1]), "=r"(r[2]), "=r"(r[3]) : "r"(a));
}
__device__ __forceinline__ void ldsm4t(uint32_t r[4], const __half* p) {
    uint32_t a = (uint32_t)__cvta_generic_to_shared(p);
    asm volatile("ldmatrix.sync.aligned.m8n8.x4.trans.shared.b16 {%0,%1,%2,%3}, [%4];"
        : "=r"(r[0]), "=r"(r[1]), "=r"(r[2]), "=r"(r[3]) : "r"(a));
}
__device__ __forceinline__ void cp16(__half* dst, const __half* src) {
    uint32_t d = (uint32_t)__cvta_generic_to_shared(dst);
    asm volatile("cp.async.cg.shared.global [%0], [%1], 16;" :: "r"(d), "l"(src));
}
__device__ __forceinline__ void cp_commit() {
    asm volatile("cp.async.commit_group;");
}
template <int N> __device__ __forceinline__ void cp_wait() {
    asm volatile("cp.async.wait_group %0;" :: "n"(N));
}

// ---------------------------------------------------------------------------
// fp32 -> fp16 pre-conversion of x and weights (one pass).
// grid: (4096, 1, 5); z selects tensor.
// ---------------------------------------------------------------------------
__global__ __launch_bounds__(256) void cvt_kernel(
    const float* __restrict__ x,
    const float* __restrict__ wq, const float* __restrict__ wk,
    const float* __restrict__ wv, const float* __restrict__ wo)
{
    const int z = blockIdx.z;
    const float* src;
    __half* dst;
    int n4;
    if      (z == 0) { src = x;  dst = g_xh;  n4 = MTOT * HH / 4; }
    else if (z == 1) { src = wq; dst = g_Wqh; n4 = HH * HH / 4; }
    else if (z == 2) { src = wk; dst = g_Wkh; n4 = HH * HH / 4; }
    else if (z == 3) { src = wv; dst = g_Wvh; n4 = HH * HH / 4; }
    else             { src = wo; dst = g_Woh; n4 = HH * HH / 4; }
    const int idx = blockIdx.x * 256 + threadIdx.x;
    if (idx < n4) {
        float4 v = ((const float4*)src)[idx];
        uint2 o;
        o.x = pack2h(v.x, v.y);
        o.y = pack2h(v.z, v.w);
        ((uint2*)dst)[idx] = o;
    }
}

// ---------------------------------------------------------------------------
// 128x128x1024 fp16 mma mainloop: R11 structure (register prefetch of next
// tile during compute, single __syncthreads per k-tile), fp16 gmem inputs.
// 256 threads, 8 warps (2m x 4n), warp tile 64x32, mma m16n8k16, BK=32.
// As[2][128][40] halfs (m,k);  Bs[2][32][136] halfs (k,n).
// ---------------------------------------------------------------------------
static constexpr int AS_ST = 40;
static constexpr int BS_ST = 136;
static constexpr int ABUF  = 128 * AS_ST;   // 5120 halfs
static constexpr int BBUF  = 32 * BS_ST;    // 4352 halfs

__device__ __forceinline__ void gemm128_mainloop_h(
    const __half* __restrict__ A, const __half* __restrict__ B,
    __half* As, __half* Bs, float acc[4][4][4])
{
    const int tid  = threadIdx.x;
    const int m0   = blockIdx.y * 128;
    const int n0   = blockIdx.x * 128;
    const int warp = tid >> 5;
    const int lane = tid & 31;
    const int warp_m = (warp >> 2) * 64;
    const int warp_n = (warp & 3) * 32;

    // ldmatrix per-lane bases
    const int la = lane & 15, lb = lane >> 4;
    const __half* aF = As + (warp_m + la) * AS_ST + lb * 8;
    const __half* bF = Bs + la * BS_ST + warp_n + lb * 8;

    // staging assignment: A 128x32 halfs (2 uint4/thread), B 32x128 halfs
    const int ar = tid >> 2,  ac = (tid & 3) * 8;     // A rows 0..63 (+64), col chunk
    const int br = tid >> 4,  bc = (tid & 15) * 8;    // B rows 0..15 (+16)

#pragma unroll
    for (int mt = 0; mt < 4; mt++)
#pragma unroll
        for (int nt = 0; nt < 4; nt++)
#pragma unroll
            for (int r = 0; r < 4; r++) acc[mt][nt][r] = 0.0f;

    const __half* ag0 = A + (size_t)(m0 + ar) * HH + ac;
    const __half* ag1 = ag0 + (size_t)64 * HH;
    const __half* bg0 = B + (size_t)br * HH + n0 + bc;
    const __half* bg1 = bg0 + (size_t)16 * HH;

    uint4 aR0 = *(const uint4*)ag0;
    uint4 aR1 = *(const uint4*)ag1;
    uint4 bR0 = *(const uint4*)bg0;
    uint4 bR1 = *(const uint4*)bg1;

    // stage tile 0 -> buffer 0
    *(uint4*)&As[ar * AS_ST + ac]          = aR0;
    *(uint4*)&As[(ar + 64) * AS_ST + ac]   = aR1;
    *(uint4*)&Bs[br * BS_ST + bc]          = bR0;
    *(uint4*)&Bs[(br + 16) * BS_ST + bc]   = bR1;
    __syncthreads();

    int cur = 0;
    for (int k0 = 0; k0 < HH; k0 += 32) {
        const bool more = (k0 + 32 < HH);
        if (more) {
            aR0 = *(const uint4*)(ag0 + k0 + 32);
            aR1 = *(const uint4*)(ag1 + k0 + 32);
            bR0 = *(const uint4*)(bg0 + (size_t)(k0 + 32) * HH);
            bR1 = *(const uint4*)(bg1 + (size_t)(k0 + 32) * HH);
        }

        const __half* aFc = aF + cur * ABUF;
        const __half* bFc = bF + cur * BBUF;
#pragma unroll
        for (int ks = 0; ks < 2; ks++) {
            uint32_t Af[4][4];
#pragma unroll
            for (int mt = 0; mt < 4; mt++)
                ldsm4(Af[mt], aFc + mt * 16 * AS_ST + ks * 16);
            uint32_t Bf[4][4];
#pragma unroll
            for (int ntp = 0; ntp < 2; ntp++)
                ldsm4t(Bf[2 * ntp], bFc + ks * 16 * BS_ST + ntp * 16);
#pragma unroll
            for (int mt = 0; mt < 4; mt++) {
                mma16(acc[mt][0], Af[mt], &Bf[0][0]);
                mma16(acc[mt][1], Af[mt], &Bf[0][2]);
                mma16(acc[mt][2], Af[mt], &Bf[2][0]);
                mma16(acc[mt][3], Af[mt], &Bf[2][2]);
            }
        }

        if (more) {
            const int nb = cur ^ 1;
            *(uint4*)&As[nb * ABUF + ar * AS_ST + ac]        = aR0;
            *(uint4*)&As[nb * ABUF + (ar + 64) * AS_ST + ac] = aR1;
            *(uint4*)&Bs[nb * BBUF + br * BS_ST + bc]        = bR0;
            *(uint4*)&Bs[nb * BBUF + (br + 16) * BS_ST + bc] = bR1;
            __syncthreads();
            cur = nb;
        }
    }
}

// ---------------------------------------------------------------------------
// QKV GEMM: out = x @ W + b (Q scaled by 0.125), fp16 out, head-major scatter.
// ---------------------------------------------------------------------------
__global__ __launch_bounds__(256, 1) void qkv_gemm_kernel(
    const float* __restrict__ bq, const float* __restrict__ bk,
    const float* __restrict__ bv)
{
    const int mat = blockIdx.z;
    const __half* W   = (mat == 0) ? g_Wqh : (mat == 1 ? g_Wkh : g_Wvh);
    const float* bias = (mat == 0) ? bq : (mat == 1 ? bk : bv);
    __half* out       = (mat == 0) ? g_Q : (mat == 1 ? g_K : g_V);
    const float osc   = (mat == 0) ? 0.125f : 1.0f;

    __shared__ __align__(16) __half As[2 * ABUF];
    __shared__ __align__(16) __half Bs[2 * BBUF];

    float acc[4][4][4];
    gemm128_mainloop_h(g_xh, W, As, Bs, acc);

    const int tid  = threadIdx.x;
    const int warp = tid >> 5;
    const int lane = tid & 31;
    const int gid  = lane >> 2;
    const int t4   = lane & 3;
    const int warp_m = (warp >> 2) * 64;
    const int warp_n = (warp & 3) * 32;
    const int m0 = blockIdx.y * 128;
    const int n0 = blockIdx.x * 128;

#pragma unroll
    for (int mt = 0; mt < 4; mt++) {
        const int mrow = m0 + warp_m + mt * 16 + gid;
#pragma unroll
        for (int nt = 0; nt < 4; nt++) {
            const int n = n0 + warp_n + nt * 8 + t4 * 2;
            const int h = n >> 6;
            const int d = n & 63;
            const float bx = bias[n], by = bias[n + 1];
            {
                int b = mrow >> 11, s = mrow & 2047;
                __half* o = out + (((size_t)(b * NH + h) * SS) + s) * HD + d;
                *(uint32_t*)o = pack2h((acc[mt][nt][0] + bx) * osc,
                                       (acc[mt][nt][1] + by) * osc);
            }
            {
                int m2 = mrow + 8;
                int b = m2 >> 11, s = m2 & 2047;
                __half* o = out + (((size_t)(b * NH + h) * SS) + s) * HD + d;
                *(uint32_t*)o = pack2h((acc[mt][nt][2] + bx) * osc,
                                       (acc[mt][nt][3] + by) * osc);
            }
        }
    }
}

// ---------------------------------------------------------------------------
// Flash attention, fp16 m16n8k16, cp.async double-buffered K/V, LDSM frags.
// 256 threads (8 warps) -> 128 q rows. smem 36.9 KB -> 2 CTAs/SM.
// (Verified structure from R11; epilogue writes fp16 ctx.)
// ---------------------------------------------------------------------------
static constexpr int FK_ST = 72;              // halfs per row
static constexpr int KVBUF = 64 * FK_ST;      // 4608 halfs

__global__ __launch_bounds__(256, 2) void flash_tc_kernel()
{
    __shared__ __align__(16) __half sm[4 * KVBUF];   // 36.9 KB

    const int bh  = blockIdx.y;     // b*NH + h
    const int b   = bh >> 4;
    const int h   = bh & 15;
    const int q0  = blockIdx.x * 128;
    const int tid = threadIdx.x;
    const int warp = tid >> 5;
    const int lane = tid & 31;
    const int gid  = lane >> 2;
    const int t4   = lane & 3;
    const int la   = lane & 15;
    const int lb   = lane >> 4;
    const unsigned F = 0xFFFFFFFFu;

    // ---- Stage Q, extract frags ----
    {
        const uint2* Qg = (const uint2*)(g_Q + ((size_t)bh * SS + q0) * HD);
#pragma unroll
        for (int i = 0; i < 8; i++) {
            int idx = tid + i * 256;
            int row = idx >> 4, c4 = idx & 15;
            *(uint2*)&sm[row * FK_ST + c4 * 4] = Qg[idx];
        }
    }
    __syncthreads();

    uint32_t Qa[4][4];
    {
        const __half* qF = sm + (warp * 16 + la) * FK_ST + lb * 8;
#pragma unroll
        for (int ks = 0; ks < 4; ks++)
            ldsm4(Qa[ks], qF + ks * 16);
    }
    __syncthreads();

    float Oc[8][4];
#pragma unroll
    for (int dt = 0; dt < 8; dt++)
#pragma unroll
        for (int r = 0; r < 4; r++) Oc[dt][r] = 0.0f;
    float m0r = -1e30f, m1r = -1e30f;
    float l0r = 0.0f,   l1r = 0.0f;

    const __half* Kgb = g_K + (size_t)bh * SS * HD;
    const __half* Vgb = g_V + (size_t)bh * SS * HD;

    const int krow_l = (lane & 7) + lb * 8;
    const int kcol_l = ((lane >> 3) & 1) * 8;

    auto issue = [&](int kt, int buf) {
        __half* Kd = sm + buf * 2 * KVBUF;
        __half* Vd = Kd + KVBUF;
        const __half* Kg = Kgb + (size_t)kt * 64 * HD;
        const __half* Vg = Vgb + (size_t)kt * 64 * HD;
#pragma unroll
        for (int i = 0; i < 2; i++) {
            int u = tid + i * 256;
            int row = u >> 3, c8 = u & 7;
            cp16(Kd + row * FK_ST + c8 * 8, Kg + row * 64 + c8 * 8);
            cp16(Vd + row * FK_ST + c8 * 8, Vg + row * 64 + c8 * 8);
        }
        cp_commit();
    };

    issue(0, 0);

    for (int kt = 0; kt < SS / 64; kt++) {
        const bool more = (kt + 1 < SS / 64);
        if (more) issue(kt + 1, (kt + 1) & 1);
        if (more) cp_wait<1>(); else cp_wait<0>();
        __syncthreads();

        const __half* Ks = sm + (kt & 1) * 2 * KVBUF;
        const __half* Vs = Ks + KVBUF;

        // ---- S = Q K^T ----
        float S[8][4];
#pragma unroll
        for (int nt = 0; nt < 8; nt++)
            S[nt][0] = S[nt][1] = S[nt][2] = S[nt][3] = 0.0f;
#pragma unroll
        for (int ks = 0; ks < 4; ks++) {
#pragma unroll
            for (int ntp = 0; ntp < 4; ntp++) {
                uint32_t bb[4];
                ldsm4(bb, Ks + (ntp * 16 + krow_l) * FK_ST + ks * 16 + kcol_l);
                mma16(S[2 * ntp],     Qa[ks], bb);
                mma16(S[2 * ntp + 1], Qa[ks], bb + 2);
            }
        }

        // ---- clip + online softmax ----
        float tmax0 = -1e30f, tmax1 = -1e30f;
#pragma unroll
        for (int nt = 0; nt < 8; nt++) {
#pragma unroll
            for (int r = 0; r < 4; r++)
                S[nt][r] = fminf(fmaxf(S[nt][r], -10000.0f), 10000.0f);
            tmax0 = fmaxf(tmax0, fmaxf(S[nt][0], S[nt][1]));
            tmax1 = fmaxf(tmax1, fmaxf(S[nt][2], S[nt][3]));
        }
        tmax0 = fmaxf(tmax0, __shfl_xor_sync(F, tmax0, 1));
        tmax0 = fmaxf(tmax0, __shfl_xor_sync(F, tmax0, 2));
        tmax1 = fmaxf(tmax1, __shfl_xor_sync(F, tmax1, 1));
        tmax1 = fmaxf(tmax1, __shfl_xor_sync(F, tmax1, 2));

        float nm0 = fmaxf(m0r, tmax0);
        float nm1 = fmaxf(m1r, tmax1);
        float al0 = __expf(m0r - nm0);
        float al1 = __expf(m1r - nm1);
        m0r = nm0; m1r = nm1;

        float sum0 = 0.0f, sum1 = 0.0f;
#pragma unroll
        for (int nt = 0; nt < 8; nt++) {
            S[nt][0] = __expf(S[nt][0] - nm0);
            S[nt][1] = __expf(S[nt][1] - nm0);
            S[nt][2] = __expf(S[nt][2] - nm1);
            S[nt][3] = __expf(S[nt][3] - nm1);
            sum0 += S[nt][0] + S[nt][1];
            sum1 += S[nt][2] + S[nt][3];
        }
        sum0 += __shfl_xor_sync(F, sum0, 1);
        sum0 += __shfl_xor_sync(F, sum0, 2);
        sum1 += __shfl_xor_sync(F, sum1, 1);
        sum1 += __shfl_xor_sync(F, sum1, 2);
        l0r = l0r * al0 + sum0;
        l1r = l1r * al1 + sum1;

#pragma unroll
        for (int dt = 0; dt < 8; dt++) {
            Oc[dt][0] *= al0; Oc[dt][1] *= al0;
            Oc[dt][2] *= al1; Oc[dt][3] *= al1;
        }

        // ---- ctx += P V ----
#pragma unroll
        for (int ks = 0; ks < 4; ks++) {
            uint32_t Pa[4];
            Pa[0] = pack2h(S[2 * ks][0],     S[2 * ks][1]);
            Pa[1] = pack2h(S[2 * ks][2],     S[2 * ks][3]);
            Pa[2] = pack2h(S[2 * ks + 1][0], S[2 * ks + 1][1]);
            Pa[3] = pack2h(S[2 * ks + 1][2], S[2 * ks + 1][3]);
            const __half* vrow = Vs + (ks * 16 + la) * FK_ST + lb * 8;
#pragma unroll
            for (int dtp = 0; dtp < 4; dtp++) {
                uint32_t bb[4];
                ldsm4t(bb, vrow + dtp * 16);
                mma16(Oc[2 * dtp],     Pa, bb);
                mma16(Oc[2 * dtp + 1], Pa, bb + 2);
            }
        }
        __syncthreads();
    }

    // ---- epilogue: normalize, write fp16 ctx ----
    const float inv0 = 1.0f / l0r;
    const float inv1 = 1.0f / l1r;
    const int srow = q0 + warp * 16 + gid;
    __half* out0 = g_ctx + ((size_t)(b * SS + srow)) * HH + h * HD;
    __half* out1 = out0 + (size_t)8 * HH;
#pragma unroll
    for (int dt = 0; dt < 8; dt++) {
        int c = dt * 8 + t4 * 2;
        *(uint32_t*)(out0 + c) = pack2h(Oc[dt][0] * inv0, Oc[dt][1] * inv0);
        *(uint32_t*)(out1 + c) = pack2h(Oc[dt][2] * inv1, Oc[dt][3] * inv1);
    }
}

// ---------------------------------------------------------------------------
// O projection: y = ctx @ Wo + bo + x   (ctx fp16, Wo fp16, residual fp32)
// ---------------------------------------------------------------------------
__global__ __launch_bounds__(256, 1) void oproj_gemm_kernel(
    const float* __restrict__ x, const float* __restrict__ bo)
{
    __shared__ __align__(16) __half As[2 * ABUF];
    __shared__ __align__(16) __half Bs[2 * BBUF];

    float acc[4][4][4];
    gemm128_mainloop_h(g_ctx, g_Woh, As, Bs, acc);

    const int tid  = threadIdx.x;
    const int warp = tid >> 5;
    const int lane = tid & 31;
    const int gid  = lane >> 2;
    const int t4   = lane & 3;
    const int warp_m = (warp >> 2) * 64;
    const int warp_n = (warp & 3) * 32;
    const int m0 = blockIdx.y * 128;
    const int n0 = blockIdx.x * 128;

#pragma unroll
    for (int mt = 0; mt < 4; mt++) {
        const int mrow = m0 + warp_m + mt * 16 + gid;
#pragma unroll
        for (int nt = 0; nt < 4; nt++) {
            const int n = n0 + warp_n + nt * 8 + t4 * 2;
            const float bx = bo[n], by = bo[n + 1];
            {
                const float* xr = x + (size_t)mrow * HH + n;
                float* yo = g_y + (size_t)mrow * HH + n;
                *(float2*)yo = make_float2(acc[mt][nt][0] + bx + xr[0],
                                           acc[mt][nt][1] + by + xr[1]);
            }
            {
                const float* xr = x + (size_t)(mrow + 8) * HH + n;
                float* yo = g_y + (size_t)(mrow + 8) * HH + n;
                *(float2*)yo = make_float2(acc[mt][nt][2] + bx + xr[0],
                                           acc[mt][nt][3] + by + xr[1]);
            }
        }
    }
}

// ---------------------------------------------------------------------------
// LayerNorm over last dim (1024): shuffle reduce, one sync.
// ---------------------------------------------------------------------------
__global__ __launch_bounds__(256) void ln_kernel(
    const float* __restrict__ gamma, const float* __restrict__ beta,
    float* __restrict__ out)
{
    __shared__ float red[16];
    const int row = blockIdx.x;
    const int tid = threadIdx.x;
    const int warp = tid >> 5;
    const int lane = tid & 31;
    const unsigned F = 0xFFFFFFFFu;

    const float4* yp = (const float4*)(g_y + (size_t)row * HH);
    float4 v = yp[tid];

    float s  = v.x + v.y + v.z + v.w;
    float sq = v.x * v.x + v.y * v.y + v.z * v.z + v.w * v.w;
#pragma unroll
    for (int off = 16; off > 0; off >>= 1) {
        s  += __shfl_xor_sync(F, s,  off);
        sq += __shfl_xor_sync(F, sq, off);
    }
    if (lane == 0) { red[warp] = s; red[8 + warp] = sq; }
    __syncthreads();

    float ts = 0.0f, tsq = 0.0f;
#pragma unroll
    for (int w = 0; w < 8; w++) { ts += red[w]; tsq += red[8 + w]; }
    const float mu  = ts * (1.0f / HH);
    const float var = tsq * (1.0f / HH) - mu * mu;
    const float inv = rsqrtf(var + 1e-5f);

    const float4 g  = ((const float4*)gamma)[tid];
    const float4 be = ((const float4*)beta)[tid];
    float4 o;
    o.x = (v.x - mu) * inv * g.x + be.x;
    o.y = (v.y - mu) * inv * g.y + be.y;
    o.z = (v.z - mu) * inv * g.z + be.z;
    o.w = (v.w - mu) * inv * g.w + be.w;
    ((float4*)out)[(size_t)row * (HH / 4) + tid] = o;
}

// ---------------------------------------------------------------------------
extern "C" void kernel_launch(void* const* d_in, const int* in_sizes, int n_in,
                              void* d_out, int out_size)
{
    (void)in_sizes; (void)n_in; (void)out_size;
    const float* x  = (const float*)d_in[0];
    const float* Wq = (const float*)d_in[1];
    const float* bq = (const float*)d_in[2];
    const float* Wk = (const float*)d_in[3];
    const float* bk = (const float*)d_in[4];
    const float* Wv = (const float*)d_in[5];
    const float* bv = (const float*)d_in[6];
    const float* Wo = (const float*)d_in[7];
    const float* bo = (const float*)d_in[8];
    const float* ga = (const float*)d_in[9];
    const float* be = (const float*)d_in[10];
    float* out = (float*)d_out;

    dim3 gc(4096, 1, 5);
    cvt_kernel<<<gc, 256>>>(x, Wq, Wk, Wv, Wo);

    dim3 gq(HH / 128, MTOT / 128, 3);
    qkv_gemm_kernel<<<gq, 256>>>(bq, bk, bv);

    dim3 gf(SS / 128, BB * NH);
    flash_tc_kernel<<<gf, 256>>>();

    dim3 go(HH / 128, MTOT / 128);
    oproj_gemm_kernel<<<go, 256>>>(x, bo);

    ln_kernel<<<MTOT, 256>>>(ga, be, out);
}